// round 4
// baseline (speedup 1.0000x reference)
#include <cuda_runtime.h>
#include <cuda_bf16.h>
#include <math.h>

// Problem constants (fixed by setup_inputs)
#define B_N 4096
#define M_N 256
#define D_N 256

#define TAU_INV_LOG2E 7.213475204444817f   // log2(e)/0.2
#define LAM_INV_LOG2E 0.18033688011112043f // log2(e)/8
#define TOPO_C 0.5f
#define LEN_C 0.01f
#define SP_C 0.001f

// ---------------- device scratch (no allocations allowed) ----------------
__device__ float g_dist[B_N * M_N];       // 4 MB
__device__ float g_factor[M_N];           // 1 + TOPO*degree[m]
__device__ float g_ep_rowsum[M_N];        // sum_j edge_prob[i][j]
__device__ float g_wl_rowsum[M_N];        // sum_j edge_prob[i][j]*protodist[i][j]
__device__ float g_part[B_N];             // per-row data_term partials

// ---------------- K0: edge probabilities, degree factor, proto distances ----------------
// grid = 256 blocks (one per prototype i), 256 threads (one per j)
__global__ void k_edges(const float* __restrict__ W, const float* __restrict__ E) {
    const int i = blockIdx.x;
    const int j = threadIdx.x;

    __shared__ float wi[D_N];
    __shared__ float red_ep[M_N];
    __shared__ float red_wl[M_N];

    wi[j] = W[i * D_N + j];
    __syncthreads();

    // symmetric edge prob, zero diagonal
    float lij = 0.5f * (E[i * M_N + j] + E[j * M_N + i]);
    float ep = __fdividef(1.0f, 1.0f + __expf(-lij));
    if (j == i) ep = 0.0f;

    // squared proto distance ||w_i - w_j||^2
    const float* wj = W + j * D_N;
    float pd = 0.0f;
#pragma unroll 8
    for (int k = 0; k < D_N; k++) {
        float d = wi[k] - wj[k];
        pd = fmaf(d, d, pd);
    }

    red_ep[j] = ep;
    red_wl[j] = ep * pd;
    __syncthreads();
    for (int s = 128; s > 0; s >>= 1) {
        if (j < s) {
            red_ep[j] += red_ep[j + s];
            red_wl[j] += red_wl[j + s];
        }
        __syncthreads();
    }
    if (j == 0) {
        float rsum = red_ep[0];
        g_ep_rowsum[i] = rsum;
        g_wl_rowsum[i] = red_wl[0];
        g_factor[i] = 1.0f + TOPO_C * (rsum / (float)(M_N - 1));
    }
}

// ---------------- K1: distances[b][m] = ||x_b - w_m|| ----------------
// Tiled: 64 b-rows x 64 m-cols per block, K chunks of 32; 256 threads, 4x4 microtile.
#define TB 64
#define TM 64
#define TK 32
#define LDT 68  // padded row stride (floats): 68*4B=272B, 16B-aligned rows, conflict-light

__global__ void k_dist(const float* __restrict__ X, const float* __restrict__ W) {
    __shared__ float As[TK][LDT]; // As[k][b]
    __shared__ float Bs[TK][LDT]; // Bs[k][m]

    const int t = threadIdx.x;
    const int tx = t & 15;        // m micro
    const int ty = t >> 4;        // b micro
    const int m0 = blockIdx.x * TM;
    const int b0 = blockIdx.y * TB;

    float acc[4][4];
#pragma unroll
    for (int i = 0; i < 4; i++)
#pragma unroll
        for (int j = 0; j < 4; j++) acc[i][j] = 0.0f;

    for (int k0 = 0; k0 < D_N; k0 += TK) {
#pragma unroll
        for (int p = 0; p < 8; p++) {
            int q = t + p * 256;   // 0..2047
            int r = q >> 5;        // row in tile (0..63)
            int c = q & 31;        // k in chunk
            As[c][r] = X[(b0 + r) * D_N + k0 + c];
            Bs[c][r] = W[(m0 + r) * D_N + k0 + c];
        }
        __syncthreads();

#pragma unroll
        for (int kk = 0; kk < TK; kk++) {
            float4 av = *(const float4*)&As[kk][ty * 4];
            float4 bv = *(const float4*)&Bs[kk][tx * 4];
            float a[4] = {av.x, av.y, av.z, av.w};
            float b[4] = {bv.x, bv.y, bv.z, bv.w};
#pragma unroll
            for (int i = 0; i < 4; i++)
#pragma unroll
                for (int j = 0; j < 4; j++) {
                    float d = a[i] - b[j];
                    acc[i][j] = fmaf(d, d, acc[i][j]);
                }
        }
        __syncthreads();
    }

#pragma unroll
    for (int i = 0; i < 4; i++) {
        int bb = b0 + ty * 4 + i;
#pragma unroll
        for (int j = 0; j < 4; j++) {
            int mm = m0 + tx * 4 + j;
            g_dist[bb * M_N + mm] = sqrtf(acc[i][j]);
        }
    }
}

// ---------------- K2: soft-rank + neighborhood + data-term partial per row ----------------
// grid = 4096 blocks (one per data point), 256 threads (one per prototype)
__global__ void k_rank() {
    const int b = blockIdx.x;
    const int t = threadIdx.x;

    __shared__ float u[M_N];
    __shared__ float red[M_N];
    __shared__ float fac_s[M_N];

    float d = g_dist[b * M_N + t];
    fac_s[t] = g_factor[t];

    // row max (for exp shift)
    red[t] = d;
    __syncthreads();
    for (int s = 128; s > 0; s >>= 1) {
        if (t < s) red[t] = fmaxf(red[t], red[t + s]);
        __syncthreads();
    }
    float dmax = red[0];
    __syncthreads();

    // u_j = exp((d_j - dmax)/tau), clamped to avoid 0/0 in far tails
    float arg = fmaxf((d - dmax) * TAU_INV_LOG2E, -100.0f);
    float ui = exp2f(arg);
    u[t] = ui;
    __syncthreads();

    // soft rank: sum_j sigmoid((d_i-d_j)/tau) = sum_j ui/(ui+uj); diagonal = 0.5
    float sum = 0.0f;
#pragma unroll 8
    for (int j = 0; j < M_N; j++) {
        sum += __fdividef(ui, ui + u[j]);
    }
    float srm1 = sum - 0.5f;              // soft_rank - 1
    float neigh = exp2f(-srm1 * LAM_INV_LOG2E);
    float contrib = neigh * d * fac_s[t];

    // deterministic block reduction
    red[t] = contrib;
    __syncthreads();
    for (int s = 128; s > 0; s >>= 1) {
        if (t < s) red[t] += red[t + s];
        __syncthreads();
    }
    if (t == 0) g_part[b] = red[0];
}

// ---------------- K3: final fixed-order reduction + loss assembly ----------------
__global__ void k_final(float* __restrict__ out) {
    const int t = threadIdx.x;
    __shared__ float red[256];

    // data term partials (4096, fixed-order strided then tree)
    float s = 0.0f;
    for (int i = t; i < B_N; i += 256) s += g_part[i];
    red[t] = s;
    __syncthreads();
    for (int k = 128; k > 0; k >>= 1) {
        if (t < k) red[t] += red[t + k];
        __syncthreads();
    }
    float data_sum = red[0];
    __syncthreads();

    // edge-prob sum
    red[t] = g_ep_rowsum[t];
    __syncthreads();
    for (int k = 128; k > 0; k >>= 1) {
        if (t < k) red[t] += red[t + k];
        __syncthreads();
    }
    float ep_sum = red[0];
    __syncthreads();

    // weighted length numerator
    red[t] = g_wl_rowsum[t];
    __syncthreads();
    for (int k = 128; k > 0; k >>= 1) {
        if (t < k) red[t] += red[t + k];
        __syncthreads();
    }
    float wl_sum = red[0];

    if (t == 0) {
        float data_term = data_sum / (float)(B_N * M_N);
        float weighted_len = wl_sum / (ep_sum + 1e-8f);
        float sparsity = ep_sum / (float)(M_N * M_N);
        out[0] = data_term + LEN_C * weighted_len + SP_C * sparsity;
    }
}

// ---------------- launch ----------------
extern "C" void kernel_launch(void* const* d_in, const int* in_sizes, int n_in,
                              void* d_out, int out_size) {
    const float* data = (const float*)d_in[0];     // [4096, 256]
    const float* weights = (const float*)d_in[1];  // [256, 256]
    const float* elog = (const float*)d_in[2];     // [256, 256]
    float* out = (float*)d_out;

    k_edges<<<M_N, M_N>>>(weights, elog);
    k_dist<<<dim3(M_N / TM, B_N / TB), 256>>>(data, weights);
    k_rank<<<B_N, M_N>>>();
    k_final<<<1, 256>>>(out);
}

// round 5
// speedup vs baseline: 2.1173x; 2.1173x over previous
#include <cuda_runtime.h>
#include <cuda_bf16.h>
#include <math.h>

// Problem constants (fixed by setup_inputs)
#define B_N 4096
#define M_N 256
#define D_N 256

#define TAU_INV_LOG2E 7.213475204444817f   // log2(e)/0.2
#define LAM_INV_LOG2E 0.18033688011112043f // log2(e)/8
#define TOPO_C 0.5f
#define LEN_C 0.01f
#define SP_C 0.001f

typedef unsigned long long u64;

// ---------------- packed f32x2 helpers (sm_103a) ----------------
__device__ __forceinline__ u64 f2add(u64 a, u64 b) {
    u64 o; asm("add.rn.f32x2 %0, %1, %2;" : "=l"(o) : "l"(a), "l"(b)); return o;
}
__device__ __forceinline__ u64 f2mul(u64 a, u64 b) {
    u64 o; asm("mul.rn.f32x2 %0, %1, %2;" : "=l"(o) : "l"(a), "l"(b)); return o;
}
__device__ __forceinline__ u64 f2fma(u64 a, u64 b, u64 c) {
    u64 o; asm("fma.rn.f32x2 %0, %1, %2, %3;" : "=l"(o) : "l"(a), "l"(b), "l"(c)); return o;
}
__device__ __forceinline__ u64 f2dup(float x) {
    u64 o; asm("mov.b64 %0, {%1, %1};" : "=l"(o) : "f"(x)); return o;
}
__device__ __forceinline__ u64 f2pack(float x, float y) {
    u64 o; asm("mov.b64 %0, {%1, %2};" : "=l"(o) : "f"(x), "f"(y)); return o;
}
__device__ __forceinline__ float2 f2unpack(u64 v) {
    float2 o; asm("mov.b64 {%0, %1}, %2;" : "=f"(o.x), "=f"(o.y) : "l"(v)); return o;
}
__device__ __forceinline__ float frcp(float x) {
    float r; asm("rcp.approx.ftz.f32 %0, %1;" : "=f"(r) : "f"(x)); return r;
}

// ---------------- device scratch (no allocations allowed) ----------------
__device__ float g_dist[B_N * M_N];       // 4 MB
__device__ float g_xsq[B_N];              // ||x_b||^2
__device__ float g_wsq[M_N];              // ||w_m||^2
__device__ float g_factor[M_N];           // 1 + TOPO*degree[m]
__device__ float g_ep_rowsum[M_N];
__device__ float g_wl_rowsum[M_N];
__device__ float g_part[B_N];             // per-row data_term partials

// ---------------- K-1: row squared norms for data and weights ----------------
// one warp per row; 4352 rows -> 544 blocks of 256 threads
__global__ void k_norms(const float* __restrict__ X, const float* __restrict__ W) {
    int gwarp = (blockIdx.x * blockDim.x + threadIdx.x) >> 5;
    int lane = threadIdx.x & 31;
    if (gwarp >= B_N + M_N) return;
    const float* row = (gwarp < B_N) ? (X + (size_t)gwarp * D_N)
                                     : (W + (size_t)(gwarp - B_N) * D_N);
    const float4* r4 = (const float4*)row;
    float s = 0.0f;
#pragma unroll
    for (int k = 0; k < D_N / 128; k++) {
        float4 v = r4[lane + k * 32];
        s = fmaf(v.x, v.x, s); s = fmaf(v.y, v.y, s);
        s = fmaf(v.z, v.z, s); s = fmaf(v.w, v.w, s);
    }
#pragma unroll
    for (int o = 16; o; o >>= 1) s += __shfl_xor_sync(0xffffffffu, s, o);
    if (lane == 0) {
        if (gwarp < B_N) g_xsq[gwarp] = s;
        else g_wsq[gwarp - B_N] = s;
    }
}

// ---------------- K0: edge probabilities, degree factor, proto distances ----------------
__global__ void k_edges(const float* __restrict__ W, const float* __restrict__ E) {
    const int i = blockIdx.x;
    const int j = threadIdx.x;
    const int lane = j & 31, warp = j >> 5;

    __shared__ __align__(16) float wi[D_N];
    __shared__ float red_ep[8];
    __shared__ float red_wl[8];

    wi[j] = W[i * D_N + j];
    __syncthreads();

    float lij = 0.5f * (E[i * M_N + j] + E[j * M_N + i]);
    float ep = __fdividef(1.0f, 1.0f + __expf(-lij));
    if (j == i) ep = 0.0f;

    const float4* wj4 = (const float4*)(W + (size_t)j * D_N);
    const float4* wi4 = (const float4*)wi;
    float dot = 0.0f;
#pragma unroll 8
    for (int k = 0; k < D_N / 4; k++) {
        float4 a = wi4[k];
        float4 b = wj4[k];
        dot = fmaf(a.x, b.x, dot);
        dot = fmaf(a.y, b.y, dot);
        dot = fmaf(a.z, b.z, dot);
        dot = fmaf(a.w, b.w, dot);
    }
    float pd = fmaxf(g_wsq[i] + g_wsq[j] - 2.0f * dot, 0.0f);

    float sep = ep, swl = ep * pd;
#pragma unroll
    for (int o = 16; o; o >>= 1) {
        sep += __shfl_xor_sync(0xffffffffu, sep, o);
        swl += __shfl_xor_sync(0xffffffffu, swl, o);
    }
    if (lane == 0) { red_ep[warp] = sep; red_wl[warp] = swl; }
    __syncthreads();
    if (j == 0) {
        float rs = 0.0f, rw = 0.0f;
#pragma unroll
        for (int w = 0; w < 8; w++) { rs += red_ep[w]; rw += red_wl[w]; }
        g_ep_rowsum[i] = rs;
        g_wl_rowsum[i] = rw;
        g_factor[i] = 1.0f + TOPO_C * (rs / (float)(M_N - 1));
    }
}

// ---------------- K1: distances[b][m] = ||x_b - w_m|| (dot-product form, packed FFMA2) ----------------
#define TB 64
#define TM 64
#define TK 32
#define LDT 68

__global__ void k_dist(const float* __restrict__ X, const float* __restrict__ W) {
    __shared__ float As[TK][LDT]; // As[k][b]
    __shared__ float Bs[TK][LDT]; // Bs[k][m]

    const int t = threadIdx.x;
    const int tx = t & 15;        // m micro
    const int ty = t >> 4;        // b micro
    const int m0 = blockIdx.x * TM;
    const int b0 = blockIdx.y * TB;

    u64 acc[4][2];
#pragma unroll
    for (int i = 0; i < 4; i++) { acc[i][0] = 0ull; acc[i][1] = 0ull; }

    for (int k0 = 0; k0 < D_N; k0 += TK) {
#pragma unroll
        for (int p = 0; p < 8; p++) {
            int q = t + p * 256;
            int r = q >> 5;
            int c = q & 31;
            As[c][r] = X[(b0 + r) * D_N + k0 + c];
            Bs[c][r] = W[(m0 + r) * D_N + k0 + c];
        }
        __syncthreads();

#pragma unroll
        for (int kk = 0; kk < TK; kk++) {
            float4 av = *(const float4*)&As[kk][ty * 4];
            float4 bv = *(const float4*)&Bs[kk][tx * 4];
            u64 b01 = f2pack(bv.x, bv.y);
            u64 b23 = f2pack(bv.z, bv.w);
            float a[4] = {av.x, av.y, av.z, av.w};
#pragma unroll
            for (int i = 0; i < 4; i++) {
                u64 ai = f2dup(a[i]);
                acc[i][0] = f2fma(ai, b01, acc[i][0]);
                acc[i][1] = f2fma(ai, b23, acc[i][1]);
            }
        }
        __syncthreads();
    }

    float xs[4], ws[4];
#pragma unroll
    for (int i = 0; i < 4; i++) xs[i] = g_xsq[b0 + ty * 4 + i];
#pragma unroll
    for (int j = 0; j < 4; j++) ws[j] = g_wsq[m0 + tx * 4 + j];
#pragma unroll
    for (int i = 0; i < 4; i++) {
        int bb = b0 + ty * 4 + i;
        float2 d01 = f2unpack(acc[i][0]);
        float2 d23 = f2unpack(acc[i][1]);
        float dots[4] = {d01.x, d01.y, d23.x, d23.y};
#pragma unroll
        for (int j = 0; j < 4; j++) {
            float dd = xs[i] + ws[j] - 2.0f * dots[j];
            g_dist[bb * M_N + m0 + tx * 4 + j] = sqrtf(fmaxf(dd, 0.0f));
        }
    }
}

// ---------------- K2: soft-rank via batched reciprocals + packed f32x2 ----------------
// sum_j ui/(ui+uj) over group {a,b,c,e}: ui * [(a+b)*ce + (c+e)*ab] * rcp(ab*ce)
// -> 1 MUFU.RCP per 4 pairs. u rescaled by 2^30 (ratio-invariant) to keep the
// 4-way products inside fp32 normal range; clamp at -60 never binds in practice.
__global__ void k_rank() {
    const int b = blockIdx.x;
    const int t = threadIdx.x;
    const int lane = t & 31, warp = t >> 5;

    __shared__ __align__(16) float us[M_N]; // interleaved: us[2k]=u_k, us[2k+1]=u_{k+128}
    __shared__ float red[8];

    float d = g_dist[b * M_N + t];

    // row max via shfl + 8-slot shared
    float m = d;
#pragma unroll
    for (int o = 16; o; o >>= 1) m = fmaxf(m, __shfl_xor_sync(0xffffffffu, m, o));
    if (lane == 0) red[warp] = m;
    __syncthreads();
    float dmax = red[0];
#pragma unroll
    for (int w = 1; w < 8; w++) dmax = fmaxf(dmax, red[w]);

    float arg = fmaxf((d - dmax) * TAU_INV_LOG2E, -60.0f) + 30.0f;
    float ui = exp2f(arg);
    us[2 * (t & 127) + (t >> 7)] = ui;
    __syncthreads();

    u64 ui2 = f2dup(ui);
    u64 acc = 0ull;
    const ulonglong2* uv = (const ulonglong2*)us;
#pragma unroll 8
    for (int it = 0; it < 32; it++) {
        ulonglong2 w0 = uv[2 * it];       // (u_{4it}|u_{4it+128}), (u_{4it+1}|u_{4it+129})
        ulonglong2 w1 = uv[2 * it + 1];   // (u_{4it+2}|...),        (u_{4it+3}|...)
        u64 a  = f2add(ui2, w0.x);
        u64 bb = f2add(ui2, w0.y);
        u64 c  = f2add(ui2, w1.x);
        u64 e  = f2add(ui2, w1.y);
        u64 ab = f2mul(a, bb);
        u64 ce = f2mul(c, e);
        u64 prod = f2mul(ab, ce);
        float2 pu = f2unpack(prod);
        u64 r = f2pack(frcp(pu.x), frcp(pu.y));
        u64 apb = f2add(a, bb);
        u64 cpe = f2add(c, e);
        u64 num = f2mul(apb, ce);
        num = f2fma(cpe, ab, num);
        acc = f2fma(num, r, acc);
    }
    float2 av = f2unpack(acc);
    float ssum = ui * (av.x + av.y);   // includes diagonal term = 0.5

    float srm1 = ssum - 0.5f;          // soft_rank - 1
    float neigh = exp2f(-srm1 * LAM_INV_LOG2E);
    float contrib = neigh * d * g_factor[t];

#pragma unroll
    for (int o = 16; o; o >>= 1) contrib += __shfl_xor_sync(0xffffffffu, contrib, o);
    __syncthreads();   // everyone done reading red[] (dmax) before reuse
    if (lane == 0) red[warp] = contrib;
    __syncthreads();
    if (t == 0) {
        float s = red[0];
#pragma unroll
        for (int w = 1; w < 8; w++) s += red[w];
        g_part[b] = s;
    }
}

// ---------------- K3: final fixed-order reduction + loss assembly ----------------
__global__ void k_final(float* __restrict__ out) {
    const int t = threadIdx.x; // 0..1023
    __shared__ float red[1024];

    // data term partials: 4096 floats = 1024 x float4
    float4 v = ((const float4*)g_part)[t];
    red[t] = (v.x + v.y) + (v.z + v.w);
    __syncthreads();
    for (int s = 512; s > 0; s >>= 1) {
        if (t < s) red[t] += red[t + s];
        __syncthreads();
    }
    float data_sum = red[0];
    __syncthreads();

    red[t] = (t < M_N) ? g_ep_rowsum[t] : 0.0f;
    __syncthreads();
    for (int s = 512; s > 0; s >>= 1) {
        if (t < s) red[t] += red[t + s];
        __syncthreads();
    }
    float ep_sum = red[0];
    __syncthreads();

    red[t] = (t < M_N) ? g_wl_rowsum[t] : 0.0f;
    __syncthreads();
    for (int s = 512; s > 0; s >>= 1) {
        if (t < s) red[t] += red[t + s];
        __syncthreads();
    }
    float wl_sum = red[0];

    if (t == 0) {
        float data_term = data_sum / (float)(B_N * M_N);
        float weighted_len = wl_sum / (ep_sum + 1e-8f);
        float sparsity = ep_sum / (float)(M_N * M_N);
        out[0] = data_term + LEN_C * weighted_len + SP_C * sparsity;
    }
}

// ---------------- launch ----------------
extern "C" void kernel_launch(void* const* d_in, const int* in_sizes, int n_in,
                              void* d_out, int out_size) {
    const float* data = (const float*)d_in[0];     // [4096, 256]
    const float* weights = (const float*)d_in[1];  // [256, 256]
    const float* elog = (const float*)d_in[2];     // [256, 256]
    float* out = (float*)d_out;

    int norm_warps = B_N + M_N;                    // 4352 rows, 1 warp each
    int norm_blocks = (norm_warps * 32 + 255) / 256;
    k_norms<<<norm_blocks, 256>>>(data, weights);
    k_edges<<<M_N, M_N>>>(weights, elog);
    k_dist<<<dim3(M_N / TM, B_N / TB), 256>>>(data, weights);
    k_rank<<<B_N, M_N>>>();
    k_final<<<1, 1024>>>(out);
}